// round 12
// baseline (speedup 1.0000x reference)
#include <cuda_runtime.h>
#include <cuda_bf16.h>
#include <cstdint>
#include <cstddef>

typedef __nv_bfloat16 bf16;

#define NN 65536
#define EE 131072
#define DD 256
#define OO 128
#define ZLD 576
#define KF 545

// ---------------------------------------------------------------------------
// Scratch: single __device__ array, carved by constexpr offsets (no allocs).
// ---------------------------------------------------------------------------
constexpr size_t SZ_XD = (size_t)NN * DD * 2;    // bf16 [N,256]
constexpr size_t SZ_AB = (size_t)NN * 512 * 2;   // bf16 [N,512]  (A1|A2)
constexpr size_t SZ_H  = (size_t)NN * DD * 2;    // bf16 [N,256]  (H1|H2)
constexpr size_t SZ_Z3 = (size_t)NN * DD * 4;    // f32  [N,256]
constexpr size_t SZ_ED = (size_t)EE * DD * 2;    // bf16 [E,256]
constexpr size_t SZ_EZ = (size_t)EE * ZLD * 2;   // bf16 [E,576]
constexpr size_t SZ_W  = (size_t)466944 * 2;     // bf16 all transposed weights

constexpr size_t OF_XH  = 0;
constexpr size_t OF_XL  = OF_XH + SZ_XD;
constexpr size_t OF_ABH = OF_XL + SZ_XD;
constexpr size_t OF_ABL = OF_ABH + SZ_AB;
constexpr size_t OF_HH  = OF_ABL + SZ_AB;
constexpr size_t OF_HL  = OF_HH + SZ_H;
constexpr size_t OF_Z3  = OF_HL + SZ_H;
constexpr size_t OF_PH  = OF_Z3 + SZ_Z3;
constexpr size_t OF_PL  = OF_PH + SZ_ED;
constexpr size_t OF_D3H = OF_PL + SZ_ED;
constexpr size_t OF_D3L = OF_D3H + SZ_ED;
constexpr size_t OF_B4H = OF_D3L + SZ_ED;
constexpr size_t OF_B4L = OF_B4H + SZ_ED;
constexpr size_t OF_ZH  = OF_B4L + SZ_ED;
constexpr size_t OF_ZL  = OF_ZH + SZ_EZ;
constexpr size_t OF_WH  = OF_ZL + SZ_EZ;
constexpr size_t OF_WL  = OF_WH + SZ_W;
constexpr size_t OF_TOTAL = OF_WL + SZ_W;

__device__ __align__(1024) unsigned char g_scratch[OF_TOTAL];

// weight sub-offsets (elements) inside the Wh / Wl regions (consecutive!)
constexpr size_t W1A = 0, W2A = 65536, W3A = 131072, W4A = 196608;
constexpr size_t W1B = 262144, W2B = 294912, W3B = 327680, W4B = 360448;
constexpr size_t WFO = 393216;  // [128, 576] K-padded

// ---------------------------------------------------------------------------
// Helpers
// ---------------------------------------------------------------------------
__device__ __forceinline__ uint32_t smem_u32(const void* p) {
    uint32_t a;
    asm("{ .reg .u64 t; cvta.to.shared.u64 t, %1; cvt.u32.u64 %0, t; }"
        : "=r"(a) : "l"(p));
    return a;
}
__device__ __forceinline__ void cp_async16(uint32_t saddr, const void* gaddr) {
    asm volatile("cp.async.cg.shared.global [%0], [%1], 16;"
                 :: "r"(saddr), "l"(gaddr) : "memory");
}
__device__ __forceinline__ void cp_commit() {
    asm volatile("cp.async.commit_group;" ::: "memory");
}
__device__ __forceinline__ void cp_wait0() {
    asm volatile("cp.async.wait_group 0;" ::: "memory");
}
__device__ __forceinline__ void cp_wait1() {
    asm volatile("cp.async.wait_group 1;" ::: "memory");
}

#define LDSM4(r, addr)                                                          \
    asm volatile("ldmatrix.sync.aligned.m8n8.x4.shared.b16 {%0,%1,%2,%3}, [%4];"\
                 : "=r"((r)[0]), "=r"((r)[1]), "=r"((r)[2]), "=r"((r)[3])       \
                 : "r"(addr))

__device__ __forceinline__ void mma16816(float* c, const uint32_t* a, const uint32_t* b) {
    asm volatile(
        "mma.sync.aligned.m16n8k16.row.col.f32.bf16.bf16.f32 "
        "{%0,%1,%2,%3}, {%4,%5,%6,%7}, {%8,%9}, {%0,%1,%2,%3};"
        : "+f"(c[0]), "+f"(c[1]), "+f"(c[2]), "+f"(c[3])
        : "r"(a[0]), "r"(a[1]), "r"(a[2]), "r"(a[3]), "r"(b[0]), "r"(b[1]));
}

__device__ __forceinline__ void fsplit(float v, bf16* h, bf16* l) {
    bf16 hh = __float2bfloat16(v);
    *h = hh;
    *l = __float2bfloat16(v - __bfloat162float(hh));
}
__device__ __forceinline__ uint32_t pack2bf(float a, float b) {
    __nv_bfloat162 t;
    t.x = __float2bfloat16(a);
    t.y = __float2bfloat16(b);
    return *(uint32_t*)&t;
}

// ---------------------------------------------------------------------------
// Weight conversion: all 9 weights in ONE launch. Transpose to [Nout, Kpad]
// K-major + hi/lo split. Segment layout matches W1A..WFO offsets exactly.
// ---------------------------------------------------------------------------
__global__ void conv_w_all(const float* __restrict__ W1a, const float* __restrict__ W2a,
                           const float* __restrict__ W3a, const float* __restrict__ W4a,
                           const float* __restrict__ W1b, const float* __restrict__ W2b,
                           const float* __restrict__ W3b, const float* __restrict__ W4b,
                           const float* __restrict__ Wf,
                           bf16* __restrict__ h, bf16* __restrict__ l) {
    int idx = blockIdx.x * 256 + threadIdx.x;   // < 466944 exactly
    const float* src;
    int base, K, Nout, Kpad;
    if (idx < 262144) {
        int seg = idx >> 16;
        src = (seg == 0) ? W1a : (seg == 1) ? W2a : (seg == 2) ? W3a : W4a;
        base = seg << 16; K = 256; Nout = 256; Kpad = 256;
    } else if (idx < 393216) {
        int seg = (idx - 262144) >> 15;
        src = (seg == 0) ? W1b : (seg == 1) ? W2b : (seg == 2) ? W3b : W4b;
        base = 262144 + (seg << 15); K = 256; Nout = 128; Kpad = 256;
    } else {
        src = Wf; base = 393216; K = KF; Nout = 128; Kpad = ZLD;
    }
    int r = idx - base;
    int n = r / Kpad, k = r % Kpad;
    float v = (k < K) ? src[(size_t)k * Nout + n] : 0.0f;
    fsplit(v, h + idx, l + idx);
}

__global__ void conv_x_kernel(const float* __restrict__ x,
                              bf16* __restrict__ h, bf16* __restrict__ l) {
    int idx = blockIdx.x * 256 + threadIdx.x;
    float v = x[idx];
    fsplit(v, h + idx, l + idx);
}

// ---------------------------------------------------------------------------
// Per-edge gather + elementwise: one warp per edge, vectorized.
// ---------------------------------------------------------------------------
__global__ void edge_prep_kernel(const float* __restrict__ x,
                                 const int* __restrict__ ei,
                                 const float* __restrict__ eattr,
                                 const float* __restrict__ Z3,
                                 const float* __restrict__ b3a,
                                 const bf16* __restrict__ Hh, const bf16* __restrict__ Hl,
                                 bf16* __restrict__ Ph, bf16* __restrict__ Pl,
                                 bf16* __restrict__ D3h, bf16* __restrict__ D3l,
                                 bf16* __restrict__ Zh, bf16* __restrict__ Zl) {
    int e = blockIdx.x * 4 + (threadIdx.x >> 5);
    int l = threadIdx.x & 31;
    int s = ei[e] & (NN - 1);
    int d = ei[EE + e] & (NN - 1);
    const float4* xs = (const float4*)(x + (size_t)s * DD);
    const float4* xd = (const float4*)(x + (size_t)d * DD);
    const float4* zs = (const float4*)(Z3 + (size_t)s * DD);
    const float4* zd = (const float4*)(Z3 + (size_t)d * DD);
    const float4* b3 = (const float4*)b3a;
    size_t eb = (size_t)e * DD;
    size_t zb = (size_t)e * ZLD;

    float dot = 0.f, ns2 = 0.f, nd2 = 0.f;
    uint32_t ph[4], pl[4], dh[4], dl[4];
#pragma unroll
    for (int i = 0; i < 2; i++) {
        int v4 = l * 2 + i;
        float4 a = xs[v4], b = xd[v4];
        float4 za = zs[v4], zc = zd[v4], bb = b3[v4];
        float p[4] = {a.x * b.x, a.y * b.y, a.z * b.z, a.w * b.w};
        dot += p[0] + p[1] + p[2] + p[3];
        ns2 += a.x * a.x + a.y * a.y + a.z * a.z + a.w * a.w;
        nd2 += b.x * b.x + b.y * b.y + b.z * b.z + b.w * b.w;
        float z[4] = {fmaxf(za.x - zc.x + bb.x, 0.f), fmaxf(za.y - zc.y + bb.y, 0.f),
                      fmaxf(za.z - zc.z + bb.z, 0.f), fmaxf(za.w - zc.w + bb.w, 0.f)};
        float phf[4], plf[4], dhf[4], dlf[4];
#pragma unroll
        for (int j = 0; j < 4; j++) {
            bf16 hh, ll;
            fsplit(p[j], &hh, &ll);
            phf[j] = __bfloat162float(hh); plf[j] = __bfloat162float(ll);
            fsplit(z[j], &hh, &ll);
            dhf[j] = __bfloat162float(hh); dlf[j] = __bfloat162float(ll);
        }
        ph[i * 2] = pack2bf(phf[0], phf[1]); ph[i * 2 + 1] = pack2bf(phf[2], phf[3]);
        pl[i * 2] = pack2bf(plf[0], plf[1]); pl[i * 2 + 1] = pack2bf(plf[2], plf[3]);
        dh[i * 2] = pack2bf(dhf[0], dhf[1]); dh[i * 2 + 1] = pack2bf(dhf[2], dhf[3]);
        dl[i * 2] = pack2bf(dlf[0], dlf[1]); dl[i * 2 + 1] = pack2bf(dlf[2], dlf[3]);
    }
    *(uint4*)(Ph + eb + l * 8)  = *(uint4*)ph;
    *(uint4*)(Pl + eb + l * 8)  = *(uint4*)pl;
    *(uint4*)(D3h + eb + l * 8) = *(uint4*)dh;
    *(uint4*)(D3l + eb + l * 8) = *(uint4*)dl;

#pragma unroll
    for (int o = 16; o; o >>= 1) {
        dot += __shfl_xor_sync(0xFFFFFFFFu, dot, o);
        ns2 += __shfl_xor_sync(0xFFFFFFFFu, ns2, o);
        nd2 += __shfl_xor_sync(0xFFFFFFFFu, nd2, o);
    }
    if (l == 0) {
        float sv = dot / (fmaxf(sqrtf(ns2), 1e-8f) * fmaxf(sqrtf(nd2), 1e-8f));
        fsplit(sv, Zh + zb + 512, Zl + zb + 512);
    }
    ((uint2*)(Zh + zb))[l]       = ((const uint2*)(Hh + (size_t)s * 256))[l];
    ((uint2*)(Zl + zb))[l]       = ((const uint2*)(Hl + (size_t)s * 256))[l];
    ((uint2*)(Zh + zb + 128))[l] = ((const uint2*)(Hh + (size_t)d * 256 + 128))[l];
    ((uint2*)(Zl + zb + 128))[l] = ((const uint2*)(Hl + (size_t)d * 256 + 128))[l];
    {
        float a = eattr[(size_t)e * 32 + l];
        fsplit(a, Zh + zb + 513 + l, Zl + zb + 513 + l);
    }
    if (l < 31) {
        Zh[zb + 545 + l] = __float2bfloat16(0.0f);
        Zl[zb + 545 + l] = __float2bfloat16(0.0f);
    }
}

// ---------------------------------------------------------------------------
// bf16x3 GEMM core: CTA tile 256x128, warp tile 64x64, 8 warps (4x2),
// 3-stage cp.async pipeline, ldmatrix fragments shared across 3 passes.
//   D = act(A[M,K] @ B[Nout,K]^T + bias);  passes Ah*Bh + Al*Bh + Ah*Bl.
// ---------------------------------------------------------------------------
#define SA 40                                // smem row stride in bf16
#define AT_B (256 * SA * 2)                  // 20480 B per A tile (hi or lo)
#define BT_B (128 * SA * 2)                  // 10240 B per B tile
#define STAGE_B (2 * AT_B + 2 * BT_B)        // 61440 B per stage
#define NSTAGE 3
#define GEMM_SMEM_BYTES (NSTAGE * STAGE_B)   // 184320

struct CoreArgs {
    const bf16 *Ah, *Al; int lda; int rowbase;   // rowbase in rows (multiple of 256)
    const bf16 *Bh, *Bl; int ldb; int nbase;
    int K;
    const float* biasT;   // 128-entry tile bias or null
    int act;              // 0 none, 1 relu, 2 tanh
    float* outF; bf16* outHi; bf16* outLo; int ldo; int outBase;
};

__device__ __forceinline__ void gemm_core(const CoreArgs g) {
    extern __shared__ char smem[];
    const uint32_t sbase = smem_u32(smem);
    const int tid = threadIdx.x, wid = tid >> 5, lane = tid & 31;
    const int quad = lane >> 2, tq = lane & 3;
    const int warpRow = wid & 3;        // 4 warps along M: 64 rows each
    const int warpCol = wid >> 2;       // 2 warps along N: 64 cols each

    const bf16* gsrc[4] = {g.Ah, g.Al, g.Bh, g.Bl};

    float acc[4][8][4] = {};
    const int nchunks = g.K >> 5;

    // 3072 x 16B per stage, 12 per thread. it<8 -> A tiles, it>=8 -> B tiles.
    auto load_stage = [&](int kc, int s) {
        const uint32_t sb0 = sbase + (uint32_t)(s * STAGE_B);
#pragma unroll
        for (int it = 0; it < 12; it++) {
            int i = tid + it * 256;
            int t, row, c4; uint32_t toff; int grow, gld;
            if (it < 8) {
                t = i >> 10; int j = i & 1023; row = j >> 2; c4 = j & 3;
                toff = (uint32_t)(t * AT_B);
                grow = g.rowbase + row; gld = g.lda;
            } else {
                int q = i - 2048;
                int t2 = q >> 9; int j = q & 511; row = j >> 2; c4 = j & 3;
                t = 2 + t2; toff = (uint32_t)(2 * AT_B + t2 * BT_B);
                grow = g.nbase + row; gld = g.ldb;
            }
            const bf16* p = gsrc[t] + (size_t)grow * gld + kc * 32 + c4 * 8;
            cp_async16(sb0 + toff + (uint32_t)(row * (SA * 2) + c4 * 16), p);
        }
        cp_commit();
    };

    // per-lane ldmatrix byte offsets within a tile
    const uint32_t aoff = (uint32_t)((lane & 15) * (SA * 2) + ((lane >> 4) & 1) * 16);
    const uint32_t boff = (uint32_t)(((lane & 7) + ((lane >> 4) & 1) * 8) * (SA * 2) +
                                     ((lane >> 3) & 1) * 16);

    load_stage(0, 0);
    if (nchunks > 1) load_stage(1, 1);

    for (int kc = 0; kc < nchunks; kc++) {
        if (kc + 1 < nchunks) cp_wait1(); else cp_wait0();
        __syncthreads();
        if (kc + 2 < nchunks) load_stage(kc + 2, (kc + 2) % NSTAGE);

        const uint32_t st = sbase + (uint32_t)((kc % NSTAGE) * STAGE_B);
#pragma unroll
        for (int k16 = 0; k16 < 2; k16++) {
            const int kk = k16 * 16;
            uint32_t ah[4][4], al[4][4];
#pragma unroll
            for (int mi = 0; mi < 4; mi++) {
                uint32_t ab = st + (uint32_t)((warpRow * 64 + mi * 16) * (SA * 2) + kk * 2) + aoff;
                LDSM4(ah[mi], ab);
                LDSM4(al[mi], ab + AT_B);
            }
#pragma unroll
            for (int nq = 0; nq < 4; nq++) {
                uint32_t bbse = st + 2 * AT_B +
                                (uint32_t)((warpCol * 64 + nq * 16) * (SA * 2) + kk * 2) + boff;
                uint32_t bh[4], bl[4];
                LDSM4(bh, bbse);
                LDSM4(bl, bbse + BT_B);
                // pass 1: Ah*Bh  (8 independent accs)
#pragma unroll
                for (int mi = 0; mi < 4; mi++) {
                    mma16816(acc[mi][nq * 2],     ah[mi], bh);
                    mma16816(acc[mi][nq * 2 + 1], ah[mi], bh + 2);
                }
                // pass 2: Al*Bh
#pragma unroll
                for (int mi = 0; mi < 4; mi++) {
                    mma16816(acc[mi][nq * 2],     al[mi], bh);
                    mma16816(acc[mi][nq * 2 + 1], al[mi], bh + 2);
                }
                // pass 3: Ah*Bl
#pragma unroll
                for (int mi = 0; mi < 4; mi++) {
                    mma16816(acc[mi][nq * 2],     ah[mi], bl);
                    mma16816(acc[mi][nq * 2 + 1], ah[mi], bl + 2);
                }
            }
        }
    }

    // ---- epilogue (packed 2-wide stores) ----
#pragma unroll
    for (int mi = 0; mi < 4; mi++)
#pragma unroll
    for (int ni = 0; ni < 8; ni++)
#pragma unroll
    for (int half = 0; half < 2; half++) {
        int row = g.rowbase + warpRow * 64 + mi * 16 + quad + half * 8;
        int c = warpCol * 64 + ni * 8 + tq * 2;
        float v0 = acc[mi][ni][half * 2], v1 = acc[mi][ni][half * 2 + 1];
        if (g.biasT) { v0 += g.biasT[c]; v1 += g.biasT[c + 1]; }
        if (g.act == 1) { v0 = fmaxf(v0, 0.f); v1 = fmaxf(v1, 0.f); }
        else if (g.act == 2) { v0 = tanhf(v0); v1 = tanhf(v1); }
        size_t o = (size_t)row * g.ldo + g.outBase + c;
        if (g.outF) {
            float2 t; t.x = v0; t.y = v1;
            *(float2*)(g.outF + o) = t;
        } else {
            bf16 h0, l0, h1, l1;
            fsplit(v0, &h0, &l0); fsplit(v1, &h1, &l1);
            __nv_bfloat162 th; th.x = h0; th.y = h1;
            __nv_bfloat162 tl; tl.x = l0; tl.y = l1;
            *(__nv_bfloat162*)(g.outHi + o) = th;
            *(__nv_bfloat162*)(g.outLo + o) = tl;
        }
    }
}

// ---- wrappers -------------------------------------------------------------
__global__ __launch_bounds__(256, 1)
void gemm_std(const bf16* Ah, const bf16* Al, int lda,
              const bf16* Bh, const bf16* Bl, int ldb, int K,
              const float* bias, int act,
              float* outF, bf16* outHi, bf16* outLo, int ldo, int colOff) {
    CoreArgs g;
    g.Ah = Ah; g.Al = Al; g.lda = lda; g.rowbase = blockIdx.x * 256;
    g.Bh = Bh; g.Bl = Bl; g.ldb = ldb; g.nbase = blockIdx.y * 128;
    g.K = K; g.biasT = bias ? bias + g.nbase : nullptr; g.act = act;
    g.outF = outF; g.outHi = outHi; g.outLo = outLo; g.ldo = ldo;
    g.outBase = colOff + g.nbase;
    gemm_core(g);
}

// Node layer-1 merged: B = [W1a;W2a;W3a] (768 rows). y 0-3 -> AB (relu,bf16x2),
// y 4-5 -> Z3 (fp32, no bias/act).
__global__ __launch_bounds__(256, 1)
void gemm_l1(const bf16* Xh, const bf16* Xl,
             const bf16* Wh, const bf16* Wl,
             const float* b1a, const float* b2a,
             bf16* ABh, bf16* ABl, float* Z3) {
    int y = blockIdx.y;
    CoreArgs g;
    g.Ah = Xh; g.Al = Xl; g.lda = 256; g.rowbase = blockIdx.x * 256;
    g.Bh = Wh; g.Bl = Wl; g.ldb = 256; g.nbase = y * 128;
    g.K = 256;
    if (y < 4) {
        g.biasT = ((y < 2) ? b1a : b2a) + (y & 1) * 128;
        g.act = 1;
        g.outF = nullptr; g.outHi = ABh; g.outLo = ABl; g.ldo = 512; g.outBase = y * 128;
    } else {
        g.biasT = nullptr; g.act = 0;
        g.outF = Z3; g.outHi = nullptr; g.outLo = nullptr; g.ldo = 256;
        g.outBase = (y - 4) * 128;
    }
    gemm_core(g);
}

// M-merged GEMM: blockIdx.x < xSplit -> branch 1, else branch 2 (256-row blocks).
__global__ __launch_bounds__(256, 1)
void gemm_mm(const bf16* A1h, const bf16* A1l,
             const bf16* A2h, const bf16* A2l, int lda, int xSplit,
             const bf16* B1h, const bf16* B1l,
             const bf16* B2h, const bf16* B2l, int ldb, int K,
             const float* bias1, const float* bias2,
             bf16* outHi, bf16* outLo, int ldo, int col1, int col2) {
    bool sec = (int)blockIdx.x >= xSplit;
    CoreArgs g;
    g.Ah = sec ? A2h : A1h; g.Al = sec ? A2l : A1l; g.lda = lda;
    g.rowbase = (sec ? ((int)blockIdx.x - xSplit) : (int)blockIdx.x) * 256;
    g.Bh = sec ? B2h : B1h; g.Bl = sec ? B2l : B1l; g.ldb = ldb; g.nbase = 0;
    g.K = K; g.biasT = sec ? bias2 : bias1; g.act = 1;
    g.outF = nullptr; g.outHi = outHi; g.outLo = outLo; g.ldo = ldo;
    g.outBase = sec ? col2 : col1;
    gemm_core(g);
}

// ---------------------------------------------------------------------------
// Host launcher
// ---------------------------------------------------------------------------
extern "C" void kernel_launch(void* const* d_in, const int* in_sizes, int n_in,
                              void* d_out, int out_size) {
    (void)in_sizes; (void)n_in; (void)out_size;
    const float* x = (const float*)d_in[0];
    const int* ei = (const int*)d_in[1];
    const float* eattr = (const float*)d_in[2];
    const float* W1a = (const float*)d_in[3];  const float* b1a = (const float*)d_in[4];
    const float* W1b = (const float*)d_in[5];  const float* b1b = (const float*)d_in[6];
    const float* W2a = (const float*)d_in[7];  const float* b2a = (const float*)d_in[8];
    const float* W2b = (const float*)d_in[9];  const float* b2b = (const float*)d_in[10];
    const float* W3a = (const float*)d_in[11]; const float* b3a = (const float*)d_in[12];
    const float* W3b = (const float*)d_in[13]; const float* b3b = (const float*)d_in[14];
    const float* W4a = (const float*)d_in[15]; const float* b4a = (const float*)d_in[16];
    const float* W4b = (const float*)d_in[17]; const float* b4b = (const float*)d_in[18];
    const float* Wf  = (const float*)d_in[19]; const float* bf_ = (const float*)d_in[20];
    float* out = (float*)d_out;

    void* basep = nullptr;
    cudaGetSymbolAddress(&basep, g_scratch);
    char* S = (char*)basep;
    bf16* Xh = (bf16*)(S + OF_XH);   bf16* Xl = (bf16*)(S + OF_XL);
    bf16* ABh = (bf16*)(S + OF_ABH); bf16* ABl = (bf16*)(S + OF_ABL);
    bf16* Hh = (bf16*)(S + OF_HH);   bf16* Hl = (bf16*)(S + OF_HL);
    float* Z3 = (float*)(S + OF_Z3);
    bf16* Ph = (bf16*)(S + OF_PH);   bf16* Pl = (bf16*)(S + OF_PL);
    bf16* D3h = (bf16*)(S + OF_D3H); bf16* D3l = (bf16*)(S + OF_D3L);
    bf16* B4h = (bf16*)(S + OF_B4H); bf16* B4l = (bf16*)(S + OF_B4L);
    bf16* Zh = (bf16*)(S + OF_ZH);   bf16* Zl = (bf16*)(S + OF_ZL);
    bf16* Wh = (bf16*)(S + OF_WH);   bf16* Wl = (bf16*)(S + OF_WL);

    cudaFuncSetAttribute(gemm_std, cudaFuncAttributeMaxDynamicSharedMemorySize, GEMM_SMEM_BYTES);
    cudaFuncSetAttribute(gemm_l1,  cudaFuncAttributeMaxDynamicSharedMemorySize, GEMM_SMEM_BYTES);
    cudaFuncSetAttribute(gemm_mm,  cudaFuncAttributeMaxDynamicSharedMemorySize, GEMM_SMEM_BYTES);

    // 1) weights (one launch) + node features
    conv_w_all<<<1824, 256>>>(W1a, W2a, W3a, W4a, W1b, W2b, W3b, W4b, Wf, Wh, Wl);
    conv_x_kernel<<<(NN * DD) / 256, 256>>>(x, Xh, Xl);

    // 2) node layer-1 merged: A1|A2 + Z3 in one launch
    gemm_l1<<<dim3(NN / 256, 6), 256, GEMM_SMEM_BYTES>>>(
        Xh, Xl, Wh + W1A, Wl + W1A, b1a, b2a, ABh, ABl, Z3);

    // 3) node layer-2 merged: H = [relu(A1@W1b+b1b) | relu(A2@W2b+b2b)]
    gemm_mm<<<dim3(2 * NN / 256, 1), 256, GEMM_SMEM_BYTES>>>(
        ABh, ABl, ABh + 256, ABl + 256, 512, NN / 256,
        Wh + W1B, Wl + W1B, Wh + W2B, Wl + W2B, 256, 256,
        b1b, b2b, Hh, Hl, 256, 0, 128);

    // 4) per-edge gather / elementwise
    edge_prep_kernel<<<EE / 4, 128>>>(x, ei, eattr, Z3, b3a, Hh, Hl,
                                      Ph, Pl, D3h, D3l, Zh, Zl);

    // 5) edge layer-1 (MLP4): B4 = relu(P@W4a+b4a)
    gemm_std<<<dim3(EE / 256, 2), 256, GEMM_SMEM_BYTES>>>(
        Ph, Pl, 256, Wh + W4A, Wl + W4A, 256, 256, b4a, 1,
        nullptr, B4h, B4l, 256, 0);

    // 6) edge layer-2 merged: z[384:512] = relu(B4@W4b+b4b), z[256:384] = relu(D3@W3b+b3b)
    gemm_mm<<<dim3(2 * EE / 256, 1), 256, GEMM_SMEM_BYTES>>>(
        B4h, B4l, D3h, D3l, 256, EE / 256,
        Wh + W4B, Wl + W4B, Wh + W3B, Wl + W3B, 256, 256,
        b4b, b3b, Zh, Zl, ZLD, 384, 256);

    // 7) final: out = tanh(z @ Wf + bf)
    gemm_std<<<dim3(EE / 256, 1), 256, GEMM_SMEM_BYTES>>>(
        Zh, Zl, ZLD, Wh + WFO, Wl + WFO, ZLD, ZLD, bf_, 2,
        out, nullptr, nullptr, 128, 0);
}

// round 14
// speedup vs baseline: 1.3012x; 1.3012x over previous
#include <cuda_runtime.h>
#include <cuda_bf16.h>
#include <cstdint>
#include <cstddef>

typedef __nv_bfloat16 bf16;

#define NN 65536
#define EE 131072
#define DD 256
#define OO 128
#define ZLD 576
#define KF 545

// ---------------------------------------------------------------------------
// Scratch: single __device__ array, carved by constexpr offsets (no allocs).
// ---------------------------------------------------------------------------
constexpr size_t SZ_XD = (size_t)NN * DD * 2;    // bf16 [N,256]
constexpr size_t SZ_AB = (size_t)NN * 512 * 2;   // bf16 [N,512]  (A1|A2)
constexpr size_t SZ_H  = (size_t)NN * DD * 2;    // bf16 [N,256]  (H1|H2)
constexpr size_t SZ_Z3 = (size_t)NN * DD * 4;    // f32  [N,256]
constexpr size_t SZ_ED = (size_t)EE * DD * 2;    // bf16 [E,256]
constexpr size_t SZ_EZ = (size_t)EE * ZLD * 2;   // bf16 [E,576]
constexpr size_t SZ_W  = (size_t)466944 * 2;     // bf16 all transposed weights

constexpr size_t OF_XH  = 0;
constexpr size_t OF_XL  = OF_XH + SZ_XD;
constexpr size_t OF_ABH = OF_XL + SZ_XD;
constexpr size_t OF_ABL = OF_ABH + SZ_AB;
constexpr size_t OF_HH  = OF_ABL + SZ_AB;
constexpr size_t OF_HL  = OF_HH + SZ_H;
constexpr size_t OF_Z3  = OF_HL + SZ_H;
constexpr size_t OF_PH  = OF_Z3 + SZ_Z3;
constexpr size_t OF_PL  = OF_PH + SZ_ED;
constexpr size_t OF_D3H = OF_PL + SZ_ED;
constexpr size_t OF_D3L = OF_D3H + SZ_ED;
constexpr size_t OF_B4H = OF_D3L + SZ_ED;
constexpr size_t OF_B4L = OF_B4H + SZ_ED;
constexpr size_t OF_ZH  = OF_B4L + SZ_ED;
constexpr size_t OF_ZL  = OF_ZH + SZ_EZ;
constexpr size_t OF_WH  = OF_ZL + SZ_EZ;
constexpr size_t OF_WL  = OF_WH + SZ_W;
constexpr size_t OF_TOTAL = OF_WL + SZ_W;

__device__ __align__(1024) unsigned char g_scratch[OF_TOTAL];

// weight sub-offsets (elements) inside the Wh / Wl regions (consecutive!)
constexpr size_t W1A = 0, W2A = 65536, W3A = 131072, W4A = 196608;
constexpr size_t W1B = 262144, W2B = 294912, W3B = 327680, W4B = 360448;
constexpr size_t WFO = 393216;  // [128, 576] K-padded

// ---------------------------------------------------------------------------
// Helpers
// ---------------------------------------------------------------------------
__device__ __forceinline__ uint32_t smem_u32(const void* p) {
    uint32_t a;
    asm("{ .reg .u64 t; cvta.to.shared.u64 t, %1; cvt.u32.u64 %0, t; }"
        : "=r"(a) : "l"(p));
    return a;
}
__device__ __forceinline__ void cp_async16(uint32_t saddr, const void* gaddr) {
    asm volatile("cp.async.cg.shared.global [%0], [%1], 16;"
                 :: "r"(saddr), "l"(gaddr) : "memory");
}
__device__ __forceinline__ void cp_commit() {
    asm volatile("cp.async.commit_group;" ::: "memory");
}
__device__ __forceinline__ void cp_wait0() {
    asm volatile("cp.async.wait_group 0;" ::: "memory");
}
__device__ __forceinline__ void cp_wait1() {
    asm volatile("cp.async.wait_group 1;" ::: "memory");
}

#define LDSM4(r, addr)                                                          \
    asm volatile("ldmatrix.sync.aligned.m8n8.x4.shared.b16 {%0,%1,%2,%3}, [%4];"\
                 : "=r"((r)[0]), "=r"((r)[1]), "=r"((r)[2]), "=r"((r)[3])       \
                 : "r"(addr))

__device__ __forceinline__ void mma16816(float* c, const uint32_t* a, const uint32_t* b) {
    asm volatile(
        "mma.sync.aligned.m16n8k16.row.col.f32.bf16.bf16.f32 "
        "{%0,%1,%2,%3}, {%4,%5,%6,%7}, {%8,%9}, {%0,%1,%2,%3};"
        : "+f"(c[0]), "+f"(c[1]), "+f"(c[2]), "+f"(c[3])
        : "r"(a[0]), "r"(a[1]), "r"(a[2]), "r"(a[3]), "r"(b[0]), "r"(b[1]));
}

__device__ __forceinline__ void fsplit(float v, bf16* h, bf16* l) {
    bf16 hh = __float2bfloat16(v);
    *h = hh;
    *l = __float2bfloat16(v - __bfloat162float(hh));
}
__device__ __forceinline__ uint32_t pack2bf(float a, float b) {
    __nv_bfloat162 t;
    t.x = __float2bfloat16(a);
    t.y = __float2bfloat16(b);
    return *(uint32_t*)&t;
}

// Swizzled smem byte offset within a 128x32bf16 tile (64B rows, no pad).
// chunk = 16B column index (0..3); swizzle key = (row>>1)&3 keeps both
// ldmatrix reads and cp.async writes conflict-free, all addrs 16B-aligned.
__device__ __forceinline__ uint32_t tile_sw(uint32_t row, uint32_t chunk) {
    return row * 64u + ((chunk ^ ((row >> 1) & 3u)) * 16u);
}

// ---------------------------------------------------------------------------
// Weight conversion: all 9 weights in ONE launch. Transpose to [Nout, Kpad]
// K-major + hi/lo split. Segment layout matches W1A..WFO offsets exactly.
// ---------------------------------------------------------------------------
__global__ void conv_w_all(const float* __restrict__ W1a, const float* __restrict__ W2a,
                           const float* __restrict__ W3a, const float* __restrict__ W4a,
                           const float* __restrict__ W1b, const float* __restrict__ W2b,
                           const float* __restrict__ W3b, const float* __restrict__ W4b,
                           const float* __restrict__ Wf,
                           bf16* __restrict__ h, bf16* __restrict__ l) {
    int idx = blockIdx.x * 256 + threadIdx.x;   // < 466944 exactly
    const float* src;
    int base, K, Nout, Kpad;
    if (idx < 262144) {
        int seg = idx >> 16;
        src = (seg == 0) ? W1a : (seg == 1) ? W2a : (seg == 2) ? W3a : W4a;
        base = seg << 16; K = 256; Nout = 256; Kpad = 256;
    } else if (idx < 393216) {
        int seg = (idx - 262144) >> 15;
        src = (seg == 0) ? W1b : (seg == 1) ? W2b : (seg == 2) ? W3b : W4b;
        base = 262144 + (seg << 15); K = 256; Nout = 128; Kpad = 256;
    } else {
        src = Wf; base = 393216; K = KF; Nout = 128; Kpad = ZLD;
    }
    int r = idx - base;
    int n = r / Kpad, k = r % Kpad;
    float v = (k < K) ? src[(size_t)k * Nout + n] : 0.0f;
    fsplit(v, h + idx, l + idx);
}

__global__ void conv_x_kernel(const float* __restrict__ x,
                              bf16* __restrict__ h, bf16* __restrict__ l) {
    int idx = blockIdx.x * 256 + threadIdx.x;
    float v = x[idx];
    fsplit(v, h + idx, l + idx);
}

// ---------------------------------------------------------------------------
// Per-edge gather + elementwise: one warp per edge, vectorized.
// ---------------------------------------------------------------------------
__global__ void edge_prep_kernel(const float* __restrict__ x,
                                 const int* __restrict__ ei,
                                 const float* __restrict__ eattr,
                                 const float* __restrict__ Z3,
                                 const float* __restrict__ b3a,
                                 const bf16* __restrict__ Hh, const bf16* __restrict__ Hl,
                                 bf16* __restrict__ Ph, bf16* __restrict__ Pl,
                                 bf16* __restrict__ D3h, bf16* __restrict__ D3l,
                                 bf16* __restrict__ Zh, bf16* __restrict__ Zl) {
    int e = blockIdx.x * 4 + (threadIdx.x >> 5);
    int l = threadIdx.x & 31;
    int s = ei[e] & (NN - 1);
    int d = ei[EE + e] & (NN - 1);
    const float4* xs = (const float4*)(x + (size_t)s * DD);
    const float4* xd = (const float4*)(x + (size_t)d * DD);
    const float4* zs = (const float4*)(Z3 + (size_t)s * DD);
    const float4* zd = (const float4*)(Z3 + (size_t)d * DD);
    const float4* b3 = (const float4*)b3a;
    size_t eb = (size_t)e * DD;
    size_t zb = (size_t)e * ZLD;

    float dot = 0.f, ns2 = 0.f, nd2 = 0.f;
    uint32_t ph[4], pl[4], dh[4], dl[4];
#pragma unroll
    for (int i = 0; i < 2; i++) {
        int v4 = l * 2 + i;
        float4 a = xs[v4], b = xd[v4];
        float4 za = zs[v4], zc = zd[v4], bb = b3[v4];
        float p[4] = {a.x * b.x, a.y * b.y, a.z * b.z, a.w * b.w};
        dot += p[0] + p[1] + p[2] + p[3];
        ns2 += a.x * a.x + a.y * a.y + a.z * a.z + a.w * a.w;
        nd2 += b.x * b.x + b.y * b.y + b.z * b.z + b.w * b.w;
        float z[4] = {fmaxf(za.x - zc.x + bb.x, 0.f), fmaxf(za.y - zc.y + bb.y, 0.f),
                      fmaxf(za.z - zc.z + bb.z, 0.f), fmaxf(za.w - zc.w + bb.w, 0.f)};
        float phf[4], plf[4], dhf[4], dlf[4];
#pragma unroll
        for (int j = 0; j < 4; j++) {
            bf16 hh, ll;
            fsplit(p[j], &hh, &ll);
            phf[j] = __bfloat162float(hh); plf[j] = __bfloat162float(ll);
            fsplit(z[j], &hh, &ll);
            dhf[j] = __bfloat162float(hh); dlf[j] = __bfloat162float(ll);
        }
        ph[i * 2] = pack2bf(phf[0], phf[1]); ph[i * 2 + 1] = pack2bf(phf[2], phf[3]);
        pl[i * 2] = pack2bf(plf[0], plf[1]); pl[i * 2 + 1] = pack2bf(plf[2], plf[3]);
        dh[i * 2] = pack2bf(dhf[0], dhf[1]); dh[i * 2 + 1] = pack2bf(dhf[2], dhf[3]);
        dl[i * 2] = pack2bf(dlf[0], dlf[1]); dl[i * 2 + 1] = pack2bf(dlf[2], dlf[3]);
    }
    *(uint4*)(Ph + eb + l * 8)  = *(uint4*)ph;
    *(uint4*)(Pl + eb + l * 8)  = *(uint4*)pl;
    *(uint4*)(D3h + eb + l * 8) = *(uint4*)dh;
    *(uint4*)(D3l + eb + l * 8) = *(uint4*)dl;

#pragma unroll
    for (int o = 16; o; o >>= 1) {
        dot += __shfl_xor_sync(0xFFFFFFFFu, dot, o);
        ns2 += __shfl_xor_sync(0xFFFFFFFFu, ns2, o);
        nd2 += __shfl_xor_sync(0xFFFFFFFFu, nd2, o);
    }
    if (l == 0) {
        float sv = dot / (fmaxf(sqrtf(ns2), 1e-8f) * fmaxf(sqrtf(nd2), 1e-8f));
        fsplit(sv, Zh + zb + 512, Zl + zb + 512);
    }
    ((uint2*)(Zh + zb))[l]       = ((const uint2*)(Hh + (size_t)s * 256))[l];
    ((uint2*)(Zl + zb))[l]       = ((const uint2*)(Hl + (size_t)s * 256))[l];
    ((uint2*)(Zh + zb + 128))[l] = ((const uint2*)(Hh + (size_t)d * 256 + 128))[l];
    ((uint2*)(Zl + zb + 128))[l] = ((const uint2*)(Hl + (size_t)d * 256 + 128))[l];
    {
        float a = eattr[(size_t)e * 32 + l];
        fsplit(a, Zh + zb + 513 + l, Zl + zb + 513 + l);
    }
    if (l < 31) {
        Zh[zb + 545 + l] = __float2bfloat16(0.0f);
        Zl[zb + 545 + l] = __float2bfloat16(0.0f);
    }
}

// ---------------------------------------------------------------------------
// bf16x3 GEMM core: CTA tile 128x128, warp tile 32x64, XOR-swizzled smem
// (64B rows, no pad), 3-stage cp.async pipeline, ONE __syncthreads per chunk.
//   D = act(A[M,K] @ B[Nout,K]^T + bias);  passes Ah*Bh + Al*Bh + Ah*Bl.
// ---------------------------------------------------------------------------
#define TILE_B (128 * 64)                    // 8192 bytes per tile (128 rows x 64B)
#define STAGE_B (4 * TILE_B)                 // 32768 bytes (Ah, Al, Bh, Bl)
#define NSTAGE 3
#define GEMM_SMEM_BYTES (NSTAGE * STAGE_B)   // 98304 -> 2 CTAs/SM (196KB)

struct CoreArgs {
    const bf16 *Ah, *Al; int lda; int rowbase;
    const bf16 *Bh, *Bl; int ldb; int nbase;
    int K;
    const float* biasT;   // 128-entry tile bias or null
    int act;              // 0 none, 1 relu, 2 tanh
    float* outF; bf16* outHi; bf16* outLo; int ldo; int outBase;
};

__device__ __forceinline__ void gemm_core(const CoreArgs g) {
    extern __shared__ char smem[];
    const uint32_t sbase = smem_u32(smem);
    const int tid = threadIdx.x, wid = tid >> 5, lane = tid & 31;
    const int quad = lane >> 2, tq = lane & 3;
    const int warpRow = wid & 3;        // 4 warps along M: 32 rows each
    const int warpCol = wid >> 2;       // 2 warps along N: 64 cols each

    const bf16* gsrc[4] = {g.Ah, g.Al, g.Bh, g.Bl};

    float acc[2][8][4] = {};
    const int nchunks = g.K >> 5;

    // 2048 x 16B per stage, 8 per thread (t = tile 0..3, row, 16B-chunk c4)
    auto load_stage = [&](int kc, int s) {
#pragma unroll
        for (int it = 0; it < 8; it++) {
            int i = tid + it * 256;
            int t = i >> 9, j = i & 511, row = j >> 2, c4 = j & 3;
            int grow = (t < 2) ? (g.rowbase + row) : (g.nbase + row);
            int gld = (t < 2) ? g.lda : g.ldb;
            const bf16* p = gsrc[t] + (size_t)grow * gld + kc * 32 + c4 * 8;
            cp_async16(sbase + (uint32_t)(s * STAGE_B + t * TILE_B) +
                       tile_sw((uint32_t)row, (uint32_t)c4), p);
        }
        cp_commit();
    };

    // per-lane ldmatrix row/chunk components
    const uint32_t arow = (uint32_t)(lane & 15);            // + warpRow*32 + mi*16
    const uint32_t achk = (uint32_t)((lane >> 4) & 1);      // + 2*k16
    const uint32_t brow = (uint32_t)((lane & 7) + ((lane >> 4) & 1) * 8);  // + warpCol*64 + nq*16
    const uint32_t bchk = (uint32_t)((lane >> 3) & 1);      // + 2*k16

    load_stage(0, 0);
    if (nchunks > 1) load_stage(1, 1);

    for (int kc = 0; kc < nchunks; kc++) {
        if (kc + 1 < nchunks) cp_wait1(); else cp_wait0();
        __syncthreads();
        if (kc + 2 < nchunks) load_stage(kc + 2, (kc + 2) % NSTAGE);

        const uint32_t st = sbase + (uint32_t)((kc % NSTAGE) * STAGE_B);
#pragma unroll
        for (int k16 = 0; k16 < 2; k16++) {
            const uint32_t ck = 2 * (uint32_t)k16;
            uint32_t ah[2][4], al[2][4];
#pragma unroll
            for (int mi = 0; mi < 2; mi++) {
                uint32_t r = (uint32_t)(warpRow * 32 + mi * 16) + arow;
                uint32_t ab = st + tile_sw(r, ck + achk);
                LDSM4(ah[mi], ab);
                LDSM4(al[mi], ab + TILE_B);
            }
#pragma unroll
            for (int nq = 0; nq < 4; nq++) {
                uint32_t r = (uint32_t)(warpCol * 64 + nq * 16) + brow;
                uint32_t bbse = st + 2 * TILE_B + tile_sw(r, ck + bchk);
                uint32_t bh[4], bl[4];
                LDSM4(bh, bbse);
                LDSM4(bl, bbse + TILE_B);
                // pass 1: Ah*Bh
#pragma unroll
                for (int mi = 0; mi < 2; mi++) {
                    mma16816(acc[mi][nq * 2],     ah[mi], bh);
                    mma16816(acc[mi][nq * 2 + 1], ah[mi], bh + 2);
                }
                // pass 2: Al*Bh
#pragma unroll
                for (int mi = 0; mi < 2; mi++) {
                    mma16816(acc[mi][nq * 2],     al[mi], bh);
                    mma16816(acc[mi][nq * 2 + 1], al[mi], bh + 2);
                }
                // pass 3: Ah*Bl
#pragma unroll
                for (int mi = 0; mi < 2; mi++) {
                    mma16816(acc[mi][nq * 2],     ah[mi], bl);
                    mma16816(acc[mi][nq * 2 + 1], ah[mi], bl + 2);
                }
            }
        }
    }

    // ---- epilogue (packed 2-wide stores) ----
#pragma unroll
    for (int mi = 0; mi < 2; mi++)
#pragma unroll
    for (int ni = 0; ni < 8; ni++)
#pragma unroll
    for (int half = 0; half < 2; half++) {
        int row = g.rowbase + warpRow * 32 + mi * 16 + quad + half * 8;
        int c = warpCol * 64 + ni * 8 + tq * 2;
        float v0 = acc[mi][ni][half * 2], v1 = acc[mi][ni][half * 2 + 1];
        if (g.biasT) { v0 += g.biasT[c]; v1 += g.biasT[c + 1]; }
        if (g.act == 1) { v0 = fmaxf(v0, 0.f); v1 = fmaxf(v1, 0.f); }
        else if (g.act == 2) { v0 = tanhf(v0); v1 = tanhf(v1); }
        size_t o = (size_t)row * g.ldo + g.outBase + c;
        if (g.outF) {
            float2 t; t.x = v0; t.y = v1;
            *(float2*)(g.outF + o) = t;
        } else {
            bf16 h0, l0, h1, l1;
            fsplit(v0, &h0, &l0); fsplit(v1, &h1, &l1);
            __nv_bfloat162 th; th.x = h0; th.y = h1;
            __nv_bfloat162 tl; tl.x = l0; tl.y = l1;
            *(__nv_bfloat162*)(g.outHi + o) = th;
            *(__nv_bfloat162*)(g.outLo + o) = tl;
        }
    }
}

// ---- wrappers -------------------------------------------------------------
__global__ __launch_bounds__(256, 2)
void gemm_std(const bf16* Ah, const bf16* Al, int lda,
              const bf16* Bh, const bf16* Bl, int ldb, int K,
              const float* bias, int act,
              float* outF, bf16* outHi, bf16* outLo, int ldo, int colOff) {
    CoreArgs g;
    g.Ah = Ah; g.Al = Al; g.lda = lda; g.rowbase = blockIdx.x * 128;
    g.Bh = Bh; g.Bl = Bl; g.ldb = ldb; g.nbase = blockIdx.y * 128;
    g.K = K; g.biasT = bias ? bias + g.nbase : nullptr; g.act = act;
    g.outF = outF; g.outHi = outHi; g.outLo = outLo; g.ldo = ldo;
    g.outBase = colOff + g.nbase;
    gemm_core(g);
}

// Node layer-1 merged: B = [W1a;W2a;W3a] (768 rows). y 0-3 -> AB (relu,bf16x2),
// y 4-5 -> Z3 (fp32, no bias/act).
__global__ __launch_bounds__(256, 2)
void gemm_l1(const bf16* Xh, const bf16* Xl,
             const bf16* Wh, const bf16* Wl,
             const float* b1a, const float* b2a,
             bf16* ABh, bf16* ABl, float* Z3) {
    int y = blockIdx.y;
    CoreArgs g;
    g.Ah = Xh; g.Al = Xl; g.lda = 256; g.rowbase = blockIdx.x * 128;
    g.Bh = Wh; g.Bl = Wl; g.ldb = 256; g.nbase = y * 128;
    g.K = 256;
    if (y < 4) {
        g.biasT = ((y < 2) ? b1a : b2a) + (y & 1) * 128;
        g.act = 1;
        g.outF = nullptr; g.outHi = ABh; g.outLo = ABl; g.ldo = 512; g.outBase = y * 128;
    } else {
        g.biasT = nullptr; g.act = 0;
        g.outF = Z3; g.outHi = nullptr; g.outLo = nullptr; g.ldo = 256;
        g.outBase = (y - 4) * 128;
    }
    gemm_core(g);
}

// M-merged GEMM: blockIdx.x < xSplit -> branch 1, else branch 2 (128-row blocks).
__global__ __launch_bounds__(256, 2)
void gemm_mm(const bf16* A1h, const bf16* A1l,
             const bf16* A2h, const bf16* A2l, int lda, int xSplit,
             const bf16* B1h, const bf16* B1l,
             const bf16* B2h, const bf16* B2l, int ldb, int K,
             const float* bias1, const float* bias2,
             bf16* outHi, bf16* outLo, int ldo, int col1, int col2) {
    bool sec = (int)blockIdx.x >= xSplit;
    CoreArgs g;
    g.Ah = sec ? A2h : A1h; g.Al = sec ? A2l : A1l; g.lda = lda;
    g.rowbase = (sec ? ((int)blockIdx.x - xSplit) : (int)blockIdx.x) * 128;
    g.Bh = sec ? B2h : B1h; g.Bl = sec ? B2l : B1l; g.ldb = ldb; g.nbase = 0;
    g.K = K; g.biasT = sec ? bias2 : bias1; g.act = 1;
    g.outF = nullptr; g.outHi = outHi; g.outLo = outLo; g.ldo = ldo;
    g.outBase = sec ? col2 : col1;
    gemm_core(g);
}

// ---------------------------------------------------------------------------
// Host launcher
// ---------------------------------------------------------------------------
extern "C" void kernel_launch(void* const* d_in, const int* in_sizes, int n_in,
                              void* d_out, int out_size) {
    (void)in_sizes; (void)n_in; (void)out_size;
    const float* x = (const float*)d_in[0];
    const int* ei = (const int*)d_in[1];
    const float* eattr = (const float*)d_in[2];
    const float* W1a = (const float*)d_in[3];  const float* b1a = (const float*)d_in[4];
    const float* W1b = (const float*)d_in[5];  const float* b1b = (const float*)d_in[6];
    const float* W2a = (const float*)d_in[7];  const float* b2a = (const float*)d_in[8];
    const float* W2b = (const float*)d_in[9];  const float* b2b = (const float*)d_in[10];
    const float* W3a = (const float*)d_in[11]; const float* b3a = (const float*)d_in[12];
    const float* W3b = (const float*)d_in[13]; const float* b3b = (const float*)d_in[14];
    const float* W4a = (const float*)d_in[15]; const float* b4a = (const float*)d_in[16];
    const float* W4b = (const float*)d_in[17]; const float* b4b = (const float*)d_in[18];
    const float* Wf  = (const float*)d_in[19]; const float* bf_ = (const float*)d_in[20];
    float* out = (float*)d_out;

    void* basep = nullptr;
    cudaGetSymbolAddress(&basep, g_scratch);
    char* S = (char*)basep;
    bf16* Xh = (bf16*)(S + OF_XH);   bf16* Xl = (bf16*)(S + OF_XL);
    bf16* ABh = (bf16*)(S + OF_ABH); bf16* ABl = (bf16*)(S + OF_ABL);
    bf16* Hh = (bf16*)(S + OF_HH);   bf16* Hl = (bf16*)(S + OF_HL);
    float* Z3 = (float*)(S + OF_Z3);
    bf16* Ph = (bf16*)(S + OF_PH);   bf16* Pl = (bf16*)(S + OF_PL);
    bf16* D3h = (bf16*)(S + OF_D3H); bf16* D3l = (bf16*)(S + OF_D3L);
    bf16* B4h = (bf16*)(S + OF_B4H); bf16* B4l = (bf16*)(S + OF_B4L);
    bf16* Zh = (bf16*)(S + OF_ZH);   bf16* Zl = (bf16*)(S + OF_ZL);
    bf16* Wh = (bf16*)(S + OF_WH);   bf16* Wl = (bf16*)(S + OF_WL);

    cudaFuncSetAttribute(gemm_std, cudaFuncAttributeMaxDynamicSharedMemorySize, GEMM_SMEM_BYTES);
    cudaFuncSetAttribute(gemm_l1,  cudaFuncAttributeMaxDynamicSharedMemorySize, GEMM_SMEM_BYTES);
    cudaFuncSetAttribute(gemm_mm,  cudaFuncAttributeMaxDynamicSharedMemorySize, GEMM_SMEM_BYTES);

    // 1) weights (one launch) + node features
    conv_w_all<<<1824, 256>>>(W1a, W2a, W3a, W4a, W1b, W2b, W3b, W4b, Wf, Wh, Wl);
    conv_x_kernel<<<(NN * DD) / 256, 256>>>(x, Xh, Xl);

    // 2) node layer-1 merged: A1|A2 + Z3 in one launch
    gemm_l1<<<dim3(NN / 128, 6), 256, GEMM_SMEM_BYTES>>>(
        Xh, Xl, Wh + W1A, Wl + W1A, b1a, b2a, ABh, ABl, Z3);

    // 3) node layer-2 merged: H = [relu(A1@W1b+b1b) | relu(A2@W2b+b2b)]
    gemm_mm<<<dim3(2 * NN / 128, 1), 256, GEMM_SMEM_BYTES>>>(
        ABh, ABl, ABh + 256, ABl + 256, 512, NN / 128,
        Wh + W1B, Wl + W1B, Wh + W2B, Wl + W2B, 256, 256,
        b1b, b2b, Hh, Hl, 256, 0, 128);

    // 4) per-edge gather / elementwise
    edge_prep_kernel<<<EE / 4, 128>>>(x, ei, eattr, Z3, b3a, Hh, Hl,
                                      Ph, Pl, D3h, D3l, Zh, Zl);

    // 5) edge layer-1 (MLP4): B4 = relu(P@W4a+b4a)
    gemm_std<<<dim3(EE / 128, 2), 256, GEMM_SMEM_BYTES>>>(
        Ph, Pl, 256, Wh + W4A, Wl + W4A, 256, 256, b4a, 1,
        nullptr, B4h, B4l, 256, 0);

    // 6) edge layer-2 merged: z[384:512] = relu(B4@W4b+b4b), z[256:384] = relu(D3@W3b+b3b)
    gemm_mm<<<dim3(2 * EE / 128, 1), 256, GEMM_SMEM_BYTES>>>(
        B4h, B4l, D3h, D3l, 256, EE / 128,
        Wh + W4B, Wl + W4B, Wh + W3B, Wl + W3B, 256, 256,
        b4b, b3b, Zh, Zl, ZLD, 384, 256);

    // 7) final: out = tanh(z @ Wf + bf)
    gemm_std<<<dim3(EE / 128, 1), 256, GEMM_SMEM_BYTES>>>(
        Zh, Zl, ZLD, Wh + WFO, Wl + WFO, ZLD, ZLD, bf_, 2,
        out, nullptr, nullptr, 128, 0);
}

// round 16
// speedup vs baseline: 1.6342x; 1.2559x over previous
#include <cuda_runtime.h>
#include <cuda_fp16.h>
#include <cstdint>
#include <cstddef>

typedef __half h16;

#define NN 65536
#define EE 131072
#define DD 256
#define OO 128
#define ZLD 576
#define KF 545

// ---------------------------------------------------------------------------
// Scratch: single __device__ array, carved by constexpr offsets (no allocs).
// ---------------------------------------------------------------------------
constexpr size_t SZ_XD = (size_t)NN * DD * 2;    // h16 [N,256]
constexpr size_t SZ_AB = (size_t)NN * 512 * 2;   // h16 [N,512]  (A1|A2)
constexpr size_t SZ_H  = (size_t)NN * DD * 2;    // h16 [N,256]  (H1|H2)
constexpr size_t SZ_Z3 = (size_t)NN * DD * 4;    // f32 [N,256]
constexpr size_t SZ_ED = (size_t)EE * DD * 2;    // h16 [E,256]
constexpr size_t SZ_EZ = (size_t)EE * ZLD * 2;   // h16 [E,576]
constexpr size_t SZ_W  = (size_t)466944 * 2;     // h16 all transposed weights

constexpr size_t OF_XH  = 0;
constexpr size_t OF_XL  = OF_XH + SZ_XD;
constexpr size_t OF_ABH = OF_XL + SZ_XD;
constexpr size_t OF_ABL = OF_ABH + SZ_AB;
constexpr size_t OF_HH  = OF_ABL + SZ_AB;
constexpr size_t OF_HL  = OF_HH + SZ_H;
constexpr size_t OF_Z3  = OF_HL + SZ_H;
constexpr size_t OF_PH  = OF_Z3 + SZ_Z3;
constexpr size_t OF_PL  = OF_PH + SZ_ED;
constexpr size_t OF_D3H = OF_PL + SZ_ED;
constexpr size_t OF_D3L = OF_D3H + SZ_ED;
constexpr size_t OF_B4H = OF_D3L + SZ_ED;
constexpr size_t OF_B4L = OF_B4H + SZ_ED;
constexpr size_t OF_ZH  = OF_B4L + SZ_ED;
constexpr size_t OF_ZL  = OF_ZH + SZ_EZ;
constexpr size_t OF_WH  = OF_ZL + SZ_EZ;
constexpr size_t OF_TOTAL = OF_WH + SZ_W;

__device__ __align__(1024) unsigned char g_scratch[OF_TOTAL];

// weight sub-offsets (elements) inside the Wh region (consecutive!)
constexpr size_t W1A = 0, W2A = 65536, W3A = 131072, W4A = 196608;
constexpr size_t W1B = 262144, W2B = 294912, W3B = 327680, W4B = 360448;
constexpr size_t WFO = 393216;  // [128, 576] K-padded

// ---------------------------------------------------------------------------
// Helpers
// ---------------------------------------------------------------------------
__device__ __forceinline__ uint32_t smem_u32(const void* p) {
    uint32_t a;
    asm("{ .reg .u64 t; cvta.to.shared.u64 t, %1; cvt.u32.u64 %0, t; }"
        : "=r"(a) : "l"(p));
    return a;
}
__device__ __forceinline__ void cp_async16(uint32_t saddr, const void* gaddr) {
    asm volatile("cp.async.cg.shared.global [%0], [%1], 16;"
                 :: "r"(saddr), "l"(gaddr) : "memory");
}
__device__ __forceinline__ void cp_commit() {
    asm volatile("cp.async.commit_group;" ::: "memory");
}
__device__ __forceinline__ void cp_wait0() {
    asm volatile("cp.async.wait_group 0;" ::: "memory");
}
__device__ __forceinline__ void cp_wait1() {
    asm volatile("cp.async.wait_group 1;" ::: "memory");
}

#define LDSM4(r, addr)                                                          \
    asm volatile("ldmatrix.sync.aligned.m8n8.x4.shared.b16 {%0,%1,%2,%3}, [%4];"\
                 : "=r"((r)[0]), "=r"((r)[1]), "=r"((r)[2]), "=r"((r)[3])       \
                 : "r"(addr))

__device__ __forceinline__ void mma16816(float* c, const uint32_t* a, const uint32_t* b) {
    asm volatile(
        "mma.sync.aligned.m16n8k16.row.col.f32.f16.f16.f32 "
        "{%0,%1,%2,%3}, {%4,%5,%6,%7}, {%8,%9}, {%0,%1,%2,%3};"
        : "+f"(c[0]), "+f"(c[1]), "+f"(c[2]), "+f"(c[3])
        : "r"(a[0]), "r"(a[1]), "r"(a[2]), "r"(a[3]), "r"(b[0]), "r"(b[1]));
}

__device__ __forceinline__ void hsplit(float v, h16* h, h16* l) {
    h16 hh = __float2half_rn(v);
    *h = hh;
    *l = __float2half_rn(v - __half2float(hh));
}
__device__ __forceinline__ uint32_t pack2h(float a, float b) {
    __half2 t = __floats2half2_rn(a, b);
    return *(uint32_t*)&t;
}

// Swizzled smem byte offset within a 128x32h16 tile (64B rows, no pad).
__device__ __forceinline__ uint32_t tile_sw(uint32_t row, uint32_t chunk) {
    return row * 64u + ((chunk ^ ((row >> 1) & 3u)) * 16u);
}

// ---------------------------------------------------------------------------
// Weight conversion: all 9 weights in ONE launch. Transpose to [Nout, Kpad]
// K-major, fp16 hi only (lo parts of B are dropped by the 2-pass scheme).
// ---------------------------------------------------------------------------
__global__ void conv_w_all(const float* __restrict__ W1a, const float* __restrict__ W2a,
                           const float* __restrict__ W3a, const float* __restrict__ W4a,
                           const float* __restrict__ W1b, const float* __restrict__ W2b,
                           const float* __restrict__ W3b, const float* __restrict__ W4b,
                           const float* __restrict__ Wf,
                           h16* __restrict__ h) {
    int idx = blockIdx.x * 256 + threadIdx.x;   // < 466944 exactly
    const float* src;
    int base, K, Nout, Kpad;
    if (idx < 262144) {
        int seg = idx >> 16;
        src = (seg == 0) ? W1a : (seg == 1) ? W2a : (seg == 2) ? W3a : W4a;
        base = seg << 16; K = 256; Nout = 256; Kpad = 256;
    } else if (idx < 393216) {
        int seg = (idx - 262144) >> 15;
        src = (seg == 0) ? W1b : (seg == 1) ? W2b : (seg == 2) ? W3b : W4b;
        base = 262144 + (seg << 15); K = 256; Nout = 128; Kpad = 256;
    } else {
        src = Wf; base = 393216; K = KF; Nout = 128; Kpad = ZLD;
    }
    int r = idx - base;
    int n = r / Kpad, k = r % Kpad;
    float v = (k < K) ? src[(size_t)k * Nout + n] : 0.0f;
    h[idx] = __float2half_rn(v);
}

__global__ void conv_x_kernel(const float* __restrict__ x,
                              h16* __restrict__ h, h16* __restrict__ l) {
    int idx = blockIdx.x * 256 + threadIdx.x;
    float v = x[idx];
    hsplit(v, h + idx, l + idx);
}

// ---------------------------------------------------------------------------
// Per-edge gather + elementwise: one warp per edge, vectorized.
// ---------------------------------------------------------------------------
__global__ void edge_prep_kernel(const float* __restrict__ x,
                                 const int* __restrict__ ei,
                                 const float* __restrict__ eattr,
                                 const float* __restrict__ Z3,
                                 const float* __restrict__ b3a,
                                 const h16* __restrict__ Hh, const h16* __restrict__ Hl,
                                 h16* __restrict__ Ph, h16* __restrict__ Pl,
                                 h16* __restrict__ D3h, h16* __restrict__ D3l,
                                 h16* __restrict__ Zh, h16* __restrict__ Zl) {
    int e = blockIdx.x * 4 + (threadIdx.x >> 5);
    int l = threadIdx.x & 31;
    int s = ei[e] & (NN - 1);
    int d = ei[EE + e] & (NN - 1);
    const float4* xs = (const float4*)(x + (size_t)s * DD);
    const float4* xd = (const float4*)(x + (size_t)d * DD);
    const float4* zs = (const float4*)(Z3 + (size_t)s * DD);
    const float4* zd = (const float4*)(Z3 + (size_t)d * DD);
    const float4* b3 = (const float4*)b3a;
    size_t eb = (size_t)e * DD;
    size_t zb = (size_t)e * ZLD;

    float dot = 0.f, ns2 = 0.f, nd2 = 0.f;
    uint32_t ph[4], pl[4], dh[4], dl[4];
#pragma unroll
    for (int i = 0; i < 2; i++) {
        int v4 = l * 2 + i;
        float4 a = xs[v4], b = xd[v4];
        float4 za = zs[v4], zc = zd[v4], bb = b3[v4];
        float p[4] = {a.x * b.x, a.y * b.y, a.z * b.z, a.w * b.w};
        dot += p[0] + p[1] + p[2] + p[3];
        ns2 += a.x * a.x + a.y * a.y + a.z * a.z + a.w * a.w;
        nd2 += b.x * b.x + b.y * b.y + b.z * b.z + b.w * b.w;
        float z[4] = {fmaxf(za.x - zc.x + bb.x, 0.f), fmaxf(za.y - zc.y + bb.y, 0.f),
                      fmaxf(za.z - zc.z + bb.z, 0.f), fmaxf(za.w - zc.w + bb.w, 0.f)};
        float phf[4], plf[4], dhf[4], dlf[4];
#pragma unroll
        for (int j = 0; j < 4; j++) {
            h16 hh, ll;
            hsplit(p[j], &hh, &ll);
            phf[j] = __half2float(hh); plf[j] = __half2float(ll);
            hsplit(z[j], &hh, &ll);
            dhf[j] = __half2float(hh); dlf[j] = __half2float(ll);
        }
        ph[i * 2] = pack2h(phf[0], phf[1]); ph[i * 2 + 1] = pack2h(phf[2], phf[3]);
        pl[i * 2] = pack2h(plf[0], plf[1]); pl[i * 2 + 1] = pack2h(plf[2], plf[3]);
        dh[i * 2] = pack2h(dhf[0], dhf[1]); dh[i * 2 + 1] = pack2h(dhf[2], dhf[3]);
        dl[i * 2] = pack2h(dlf[0], dlf[1]); dl[i * 2 + 1] = pack2h(dlf[2], dlf[3]);
    }
    *(uint4*)(Ph + eb + l * 8)  = *(uint4*)ph;
    *(uint4*)(Pl + eb + l * 8)  = *(uint4*)pl;
    *(uint4*)(D3h + eb + l * 8) = *(uint4*)dh;
    *(uint4*)(D3l + eb + l * 8) = *(uint4*)dl;

#pragma unroll
    for (int o = 16; o; o >>= 1) {
        dot += __shfl_xor_sync(0xFFFFFFFFu, dot, o);
        ns2 += __shfl_xor_sync(0xFFFFFFFFu, ns2, o);
        nd2 += __shfl_xor_sync(0xFFFFFFFFu, nd2, o);
    }
    if (l == 0) {
        float sv = dot / (fmaxf(sqrtf(ns2), 1e-8f) * fmaxf(sqrtf(nd2), 1e-8f));
        hsplit(sv, Zh + zb + 512, Zl + zb + 512);
    }
    ((uint2*)(Zh + zb))[l]       = ((const uint2*)(Hh + (size_t)s * 256))[l];
    ((uint2*)(Zl + zb))[l]       = ((const uint2*)(Hl + (size_t)s * 256))[l];
    ((uint2*)(Zh + zb + 128))[l] = ((const uint2*)(Hh + (size_t)d * 256 + 128))[l];
    ((uint2*)(Zl + zb + 128))[l] = ((const uint2*)(Hl + (size_t)d * 256 + 128))[l];
    {
        float a = eattr[(size_t)e * 32 + l];
        hsplit(a, Zh + zb + 513 + l, Zl + zb + 513 + l);
    }
    if (l < 31) {
        Zh[zb + 545 + l] = __float2half_rn(0.0f);
        Zl[zb + 545 + l] = __float2half_rn(0.0f);
    }
}

// ---------------------------------------------------------------------------
// fp16x2 GEMM core: CTA tile 128x128, warp tile 32x64, XOR-swizzled smem,
// 3-stage cp.async pipeline, ONE __syncthreads per chunk.
//   D = act(A[M,K] @ B[Nout,K]^T + bias);  passes (Ah + Al) * Bh.
// ---------------------------------------------------------------------------
#define TILE_B (128 * 64)                    // 8192 bytes per tile
#define STAGE_B (3 * TILE_B)                 // 24576 bytes (Ah, Al, Bh)
#define NSTAGE 3
#define GEMM_SMEM_BYTES (NSTAGE * STAGE_B)   // 73728 -> 2 CTAs/SM (147KB)

struct CoreArgs {
    const h16 *Ah, *Al; int lda; int rowbase;
    const h16 *Bh; int ldb; int nbase;
    int K;
    const float* biasT;   // 128-entry tile bias or null
    int act;              // 0 none, 1 relu, 2 tanh
    float* outF; h16* outHi; h16* outLo; int ldo; int outBase;
};

__device__ __forceinline__ void gemm_core(const CoreArgs g) {
    extern __shared__ char smem[];
    const uint32_t sbase = smem_u32(smem);
    const int tid = threadIdx.x, wid = tid >> 5, lane = tid & 31;
    const int quad = lane >> 2, tq = lane & 3;
    const int warpRow = wid & 3;        // 4 warps along M: 32 rows each
    const int warpCol = wid >> 2;       // 2 warps along N: 64 cols each

    const h16* gsrc[3] = {g.Ah, g.Al, g.Bh};

    float acc[2][8][4] = {};
    const int nchunks = g.K >> 5;

    // 1536 x 16B per stage, 6 per thread (t = tile 0..2, row, 16B-chunk c4)
    auto load_stage = [&](int kc, int s) {
#pragma unroll
        for (int it = 0; it < 6; it++) {
            int i = tid + it * 256;
            int t = i >> 9, j = i & 511, row = j >> 2, c4 = j & 3;
            int grow = (t < 2) ? (g.rowbase + row) : (g.nbase + row);
            int gld = (t < 2) ? g.lda : g.ldb;
            const h16* p = gsrc[t] + (size_t)grow * gld + kc * 32 + c4 * 8;
            cp_async16(sbase + (uint32_t)(s * STAGE_B + t * TILE_B) +
                       tile_sw((uint32_t)row, (uint32_t)c4), p);
        }
        cp_commit();
    };

    // per-lane ldmatrix row/chunk components
    const uint32_t arow = (uint32_t)(lane & 15);
    const uint32_t achk = (uint32_t)((lane >> 4) & 1);
    const uint32_t brow = (uint32_t)((lane & 7) + ((lane >> 4) & 1) * 8);
    const uint32_t bchk = (uint32_t)((lane >> 3) & 1);

    load_stage(0, 0);
    if (nchunks > 1) load_stage(1, 1);

    for (int kc = 0; kc < nchunks; kc++) {
        if (kc + 1 < nchunks) cp_wait1(); else cp_wait0();
        __syncthreads();
        if (kc + 2 < nchunks) load_stage(kc + 2, (kc + 2) % NSTAGE);

        const uint32_t st = sbase + (uint32_t)((kc % NSTAGE) * STAGE_B);
#pragma unroll
        for (int k16 = 0; k16 < 2; k16++) {
            const uint32_t ck = 2 * (uint32_t)k16;
            uint32_t ah[2][4], al[2][4];
#pragma unroll
            for (int mi = 0; mi < 2; mi++) {
                uint32_t r = (uint32_t)(warpRow * 32 + mi * 16) + arow;
                uint32_t ab = st + tile_sw(r, ck + achk);
                LDSM4(ah[mi], ab);
                LDSM4(al[mi], ab + TILE_B);
            }
#pragma unroll
            for (int nq = 0; nq < 4; nq++) {
                uint32_t r = (uint32_t)(warpCol * 64 + nq * 16) + brow;
                uint32_t bbse = st + 2 * TILE_B + tile_sw(r, ck + bchk);
                uint32_t bh[4];
                LDSM4(bh, bbse);
                // pass 1: Ah*Bh
#pragma unroll
                for (int mi = 0; mi < 2; mi++) {
                    mma16816(acc[mi][nq * 2],     ah[mi], bh);
                    mma16816(acc[mi][nq * 2 + 1], ah[mi], bh + 2);
                }
                // pass 2: Al*Bh
#pragma unroll
                for (int mi = 0; mi < 2; mi++) {
                    mma16816(acc[mi][nq * 2],     al[mi], bh);
                    mma16816(acc[mi][nq * 2 + 1], al[mi], bh + 2);
                }
            }
        }
    }

    // ---- epilogue (packed 2-wide stores) ----
#pragma unroll
    for (int mi = 0; mi < 2; mi++)
#pragma unroll
    for (int ni = 0; ni < 8; ni++)
#pragma unroll
    for (int half = 0; half < 2; half++) {
        int row = g.rowbase + warpRow * 32 + mi * 16 + quad + half * 8;
        int c = warpCol * 64 + ni * 8 + tq * 2;
        float v0 = acc[mi][ni][half * 2], v1 = acc[mi][ni][half * 2 + 1];
        if (g.biasT) { v0 += g.biasT[c]; v1 += g.biasT[c + 1]; }
        if (g.act == 1) { v0 = fmaxf(v0, 0.f); v1 = fmaxf(v1, 0.f); }
        else if (g.act == 2) { v0 = tanhf(v0); v1 = tanhf(v1); }
        size_t o = (size_t)row * g.ldo + g.outBase + c;
        if (g.outF) {
            float2 t; t.x = v0; t.y = v1;
            *(float2*)(g.outF + o) = t;
        } else {
            h16 h0, l0, h1, l1;
            hsplit(v0, &h0, &l0); hsplit(v1, &h1, &l1);
            __half2 th; th.x = h0; th.y = h1;
            __half2 tl; tl.x = l0; tl.y = l1;
            *(__half2*)(g.outHi + o) = th;
            *(__half2*)(g.outLo + o) = tl;
        }
    }
}

// ---- wrappers -------------------------------------------------------------
__global__ __launch_bounds__(256, 2)
void gemm_std(const h16* Ah, const h16* Al, int lda,
              const h16* Bh, int ldb, int K,
              const float* bias, int act,
              float* outF, h16* outHi, h16* outLo, int ldo, int colOff) {
    CoreArgs g;
    g.Ah = Ah; g.Al = Al; g.lda = lda; g.rowbase = blockIdx.x * 128;
    g.Bh = Bh; g.ldb = ldb; g.nbase = blockIdx.y * 128;
    g.K = K; g.biasT = bias ? bias + g.nbase : nullptr; g.act = act;
    g.outF = outF; g.outHi = outHi; g.outLo = outLo; g.ldo = ldo;
    g.outBase = colOff + g.nbase;
    gemm_core(g);
}

// Node layer-1 merged: B = [W1a;W2a;W3a] (768 rows). y 0-3 -> AB (relu,h16x2),
// y 4-5 -> Z3 (fp32, no bias/act).
__global__ __launch_bounds__(256, 2)
void gemm_l1(const h16* Xh, const h16* Xl,
             const h16* Wh,
             const float* b1a, const float* b2a,
             h16* ABh, h16* ABl, float* Z3) {
    int y = blockIdx.y;
    CoreArgs g;
    g.Ah = Xh; g.Al = Xl; g.lda = 256; g.rowbase = blockIdx.x * 128;
    g.Bh = Wh; g.ldb = 256; g.nbase = y * 128;
    g.K = 256;
    if (y < 4) {
        g.biasT = ((y < 2) ? b1a : b2a) + (y & 1) * 128;
        g.act = 1;
        g.outF = nullptr; g.outHi = ABh; g.outLo = ABl; g.ldo = 512; g.outBase = y * 128;
    } else {
        g.biasT = nullptr; g.act = 0;
        g.outF = Z3; g.outHi = nullptr; g.outLo = nullptr; g.ldo = 256;
        g.outBase = (y - 4) * 128;
    }
    gemm_core(g);
}

// M-merged GEMM: blockIdx.x < xSplit -> branch 1, else branch 2 (128-row blocks).
__global__ __launch_bounds__(256, 2)
void gemm_mm(const h16* A1h, const h16* A1l,
             const h16* A2h, const h16* A2l, int lda, int xSplit,
             const h16* B1h, const h16* B2h, int ldb, int K,
             const float* bias1, const float* bias2,
             h16* outHi, h16* outLo, int ldo, int col1, int col2) {
    bool sec = (int)blockIdx.x >= xSplit;
    CoreArgs g;
    g.Ah = sec ? A2h : A1h; g.Al = sec ? A2l : A1l; g.lda = lda;
    g.rowbase = (sec ? ((int)blockIdx.x - xSplit) : (int)blockIdx.x) * 128;
    g.Bh = sec ? B2h : B1h; g.ldb = ldb; g.nbase = 0;
    g.K = K; g.biasT = sec ? bias2 : bias1; g.act = 1;
    g.outF = nullptr; g.outHi = outHi; g.outLo = outLo; g.ldo = ldo;
    g.outBase = sec ? col2 : col1;
    gemm_core(g);
}

// ---------------------------------------------------------------------------
// Host launcher
// ---------------------------------------------------------------------------
extern "C" void kernel_launch(void* const* d_in, const int* in_sizes, int n_in,
                              void* d_out, int out_size) {
    (void)in_sizes; (void)n_in; (void)out_size;
    const float* x = (const float*)d_in[0];
    const int* ei = (const int*)d_in[1];
    const float* eattr = (const float*)d_in[2];
    const float* W1a = (const float*)d_in[3];  const float* b1a = (const float*)d_in[4];
    const float* W1b = (const float*)d_in[5];  const float* b1b = (const float*)d_in[6];
    const float* W2a = (const float*)d_in[7];  const float* b2a = (const float*)d_in[8];
    const float* W2b = (const float*)d_in[9];  const float* b2b = (const float*)d_in[10];
    const float* W3a = (const float*)d_in[11]; const float* b3a = (const float*)d_in[12];
    const float* W3b = (const float*)d_in[13]; const float* b3b = (const float*)d_in[14];
    const float* W4a = (const float*)d_in[15]; const float* b4a = (const float*)d_in[16];
    const float* W4b = (const float*)d_in[17]; const float* b4b = (const float*)d_in[18];
    const float* Wf  = (const float*)d_in[19]; const float* bf_ = (const float*)d_in[20];
    float* out = (float*)d_out;

    void* basep = nullptr;
    cudaGetSymbolAddress(&basep, g_scratch);
    char* S = (char*)basep;
    h16* Xh = (h16*)(S + OF_XH);   h16* Xl = (h16*)(S + OF_XL);
    h16* ABh = (h16*)(S + OF_ABH); h16* ABl = (h16*)(S + OF_ABL);
    h16* Hh = (h16*)(S + OF_HH);   h16* Hl = (h16*)(S + OF_HL);
    float* Z3 = (float*)(S + OF_Z3);
    h16* Ph = (h16*)(S + OF_PH);   h16* Pl = (h16*)(S + OF_PL);
    h16* D3h = (h16*)(S + OF_D3H); h16* D3l = (h16*)(S + OF_D3L);
    h16* B4h = (h16*)(S + OF_B4H); h16* B4l = (h16*)(S + OF_B4L);
    h16* Zh = (h16*)(S + OF_ZH);   h16* Zl = (h16*)(S + OF_ZL);
    h16* Wh = (h16*)(S + OF_WH);

    cudaFuncSetAttribute(gemm_std, cudaFuncAttributeMaxDynamicSharedMemorySize, GEMM_SMEM_BYTES);
    cudaFuncSetAttribute(gemm_l1,  cudaFuncAttributeMaxDynamicSharedMemorySize, GEMM_SMEM_BYTES);
    cudaFuncSetAttribute(gemm_mm,  cudaFuncAttributeMaxDynamicSharedMemorySize, GEMM_SMEM_BYTES);

    // 1) weights (one launch) + node features
    conv_w_all<<<1824, 256>>>(W1a, W2a, W3a, W4a, W1b, W2b, W3b, W4b, Wf, Wh);
    conv_x_kernel<<<(NN * DD) / 256, 256>>>(x, Xh, Xl);

    // 2) node layer-1 merged: A1|A2 + Z3 in one launch
    gemm_l1<<<dim3(NN / 128, 6), 256, GEMM_SMEM_BYTES>>>(
        Xh, Xl, Wh + W1A, b1a, b2a, ABh, ABl, Z3);

    // 3) node layer-2 merged: H = [relu(A1@W1b+b1b) | relu(A2@W2b+b2b)]
    gemm_mm<<<dim3(2 * NN / 128, 1), 256, GEMM_SMEM_BYTES>>>(
        ABh, ABl, ABh + 256, ABl + 256, 512, NN / 128,
        Wh + W1B, Wh + W2B, 256, 256,
        b1b, b2b, Hh, Hl, 256, 0, 128);

    // 4) per-edge gather / elementwise
    edge_prep_kernel<<<EE / 4, 128>>>(x, ei, eattr, Z3, b3a, Hh, Hl,
                                      Ph, Pl, D3h, D3l, Zh, Zl);

    // 5) edge layer-1 (MLP4): B4 = relu(P@W4a+b4a)
    gemm_std<<<dim3(EE / 128, 2), 256, GEMM_SMEM_BYTES>>>(
        Ph, Pl, 256, Wh + W4A, 256, 256, b4a, 1,
        nullptr, B4h, B4l, 256, 0);

    // 6) edge layer-2 merged: z[384:512] = relu(B4@W4b+b4b), z[256:384] = relu(D3@W3b+b3b)
    gemm_mm<<<dim3(2 * EE / 128, 1), 256, GEMM_SMEM_BYTES>>>(
        B4h, B4l, D3h, D3l, 256, EE / 128,
        Wh + W4B, Wh + W3B, 256, 256,
        b4b, b3b, Zh, Zl, ZLD, 384, 256);

    // 7) final: out = tanh(z @ Wf + bf)
    gemm_std<<<dim3(EE / 128, 1), 256, GEMM_SMEM_BYTES>>>(
        Zh, Zl, ZLD, Wh + WFO, ZLD, ZLD, bf_, 2,
        out, nullptr, nullptr, 128, 0);
}